// round 4
// baseline (speedup 1.0000x reference)
#include <cuda_runtime.h>
#include <cuda_bf16.h>
#include <cstdint>

// MaxAggregator: out[n, :] = max over s of features[neighbor_idx[n, s], :]
// N = 100000 nodes, S = 10 samples, D = 256 features (fp32).
//
// R4: stop the output write stream from evicting the feature table out of L2.
//  - output stores: st.global.wt (write-through, no dirty L2 allocation)
//  - feature gathers: ld.global.nc + evict_last cache hint (kept)
//  - across CUDA-graph replays the 102MB table should converge to resident
//    in the 126MB L2 -> gather becomes L2-hit, DRAM ~ output-only.

#define NUM_SAMPLE 10
#define D_FEAT 256
#define CHUNKS_PER_NODE (D_FEAT / 4)   // 64 float4 per node

__device__ __forceinline__ float4 ldg_keep(const float4* p, uint64_t pol) {
    float4 v;
    asm("ld.global.nc.L2::cache_hint.v4.f32 {%0,%1,%2,%3}, [%4], %5;"
        : "=f"(v.x), "=f"(v.y), "=f"(v.z), "=f"(v.w)
        : "l"(p), "l"(pol));
    return v;
}

__device__ __forceinline__ void stg_wt(float4* p, float4 v) {
    asm volatile("st.global.wt.v4.f32 [%0], {%1,%2,%3,%4};"
        :: "l"(p), "f"(v.x), "f"(v.y), "f"(v.z), "f"(v.w) : "memory");
}

__global__ void __launch_bounds__(256) max_agg_kernel(
    const int* __restrict__ neighbor_idx,   // [N, 10]
    const float* __restrict__ features,     // [U, 256]
    float* __restrict__ out,                // [N, 256]
    int n_nodes)
{
    long long g = (long long)blockIdx.x * blockDim.x + threadIdx.x;
    int node = (int)(g >> 6);          // g / 64
    int chunk = (int)(g & 63);         // g % 64
    if (node >= n_nodes) return;

    uint64_t pol;
    asm("createpolicy.fractional.L2::evict_last.b64 %0, 1.0;" : "=l"(pol));

    // idx row = 40 bytes, 8B-aligned -> 5x int2 (broadcast across the node's
    // threads; L1-served after first warp touch).
    const int2* idx2 = (const int2*)(neighbor_idx + (long long)node * NUM_SAMPLE);
    int2 p0 = __ldg(idx2 + 0);
    int2 p1 = __ldg(idx2 + 1);
    int2 p2 = __ldg(idx2 + 2);
    int2 p3 = __ldg(idx2 + 3);
    int2 p4 = __ldg(idx2 + 4);

    const float4* f4 = (const float4*)features;
    long long c = chunk;

    // 10 independent gathered loads -> MLP=10 hides L2/DRAM latency.
    float4 v0 = ldg_keep(f4 + (long long)p0.x * CHUNKS_PER_NODE + c, pol);
    float4 v1 = ldg_keep(f4 + (long long)p0.y * CHUNKS_PER_NODE + c, pol);
    float4 v2 = ldg_keep(f4 + (long long)p1.x * CHUNKS_PER_NODE + c, pol);
    float4 v3 = ldg_keep(f4 + (long long)p1.y * CHUNKS_PER_NODE + c, pol);
    float4 v4 = ldg_keep(f4 + (long long)p2.x * CHUNKS_PER_NODE + c, pol);
    float4 v5 = ldg_keep(f4 + (long long)p2.y * CHUNKS_PER_NODE + c, pol);
    float4 v6 = ldg_keep(f4 + (long long)p3.x * CHUNKS_PER_NODE + c, pol);
    float4 v7 = ldg_keep(f4 + (long long)p3.y * CHUNKS_PER_NODE + c, pol);
    float4 v8 = ldg_keep(f4 + (long long)p4.x * CHUNKS_PER_NODE + c, pol);
    float4 v9 = ldg_keep(f4 + (long long)p4.y * CHUNKS_PER_NODE + c, pol);

    float4 m;
    m.x = fmaxf(v0.x, v1.x); m.y = fmaxf(v0.y, v1.y);
    m.z = fmaxf(v0.z, v1.z); m.w = fmaxf(v0.w, v1.w);
    m.x = fmaxf(m.x, v2.x);  m.y = fmaxf(m.y, v2.y);
    m.z = fmaxf(m.z, v2.z);  m.w = fmaxf(m.w, v2.w);
    m.x = fmaxf(m.x, v3.x);  m.y = fmaxf(m.y, v3.y);
    m.z = fmaxf(m.z, v3.z);  m.w = fmaxf(m.w, v3.w);
    m.x = fmaxf(m.x, v4.x);  m.y = fmaxf(m.y, v4.y);
    m.z = fmaxf(m.z, v4.z);  m.w = fmaxf(m.w, v4.w);
    m.x = fmaxf(m.x, v5.x);  m.y = fmaxf(m.y, v5.y);
    m.z = fmaxf(m.z, v5.z);  m.w = fmaxf(m.w, v5.w);
    m.x = fmaxf(m.x, v6.x);  m.y = fmaxf(m.y, v6.y);
    m.z = fmaxf(m.z, v6.z);  m.w = fmaxf(m.w, v6.w);
    m.x = fmaxf(m.x, v7.x);  m.y = fmaxf(m.y, v7.y);
    m.z = fmaxf(m.z, v7.z);  m.w = fmaxf(m.w, v7.w);
    m.x = fmaxf(m.x, v8.x);  m.y = fmaxf(m.y, v8.y);
    m.z = fmaxf(m.z, v8.z);  m.w = fmaxf(m.w, v8.w);
    m.x = fmaxf(m.x, v9.x);  m.y = fmaxf(m.y, v9.y);
    m.z = fmaxf(m.z, v9.z);  m.w = fmaxf(m.w, v9.w);

    stg_wt((float4*)out + (long long)node * CHUNKS_PER_NODE + c, m);
}

extern "C" void kernel_launch(void* const* d_in, const int* in_sizes, int n_in,
                              void* d_out, int out_size) {
    const int* neighbor_idx = (const int*)d_in[0];       // [N, 10] int32
    const float* features   = (const float*)d_in[1];     // [U, 256] fp32
    float* out = (float*)d_out;

    int n_nodes = in_sizes[0] / NUM_SAMPLE;              // 100000

    long long total_threads = (long long)n_nodes * CHUNKS_PER_NODE;  // 6.4M
    int block = 256;
    int grid = (int)((total_threads + block - 1) / block);

    max_agg_kernel<<<grid, block>>>(neighbor_idx, features, out, n_nodes);
}

// round 5
// speedup vs baseline: 1.1577x; 1.1577x over previous
#include <cuda_runtime.h>
#include <cuda_bf16.h>
#include <cstdint>

// MaxAggregator: out[n, :] = max over s of features[neighbor_idx[n, s], :]
// N = 100000 nodes, S = 10 samples, D = 256 features (fp32).
//
// R5: COLUMN TILING for L2 locality. Process D in 4 tiles of 64 columns.
// Grid is ordered tile-major: all blocks of tile 0 first (~5 waves), then
// tile 1, ... Within a tile the gathered table slice is only
// 100K x 64 x 4B = 25.6 MB -> resident in the 126 MB L2, so the ~10x
// per-row reuse is served from L2 instead of DRAM.
// DRAM/launch drops ~433 MB -> ~220 MB (compulsory-ish).

#define NUM_SAMPLE 10
#define D_FEAT 256
#define N_TILES 4
#define TILE_COLS (D_FEAT / N_TILES)          // 64 cols
#define TILE_CHUNKS (TILE_COLS / 4)           // 16 float4 per node per tile
#define ROW_CHUNKS (D_FEAT / 4)               // 64 float4 per full row
#define THREADS_PER_NODE TILE_CHUNKS          // 16

__global__ void __launch_bounds__(256) max_agg_kernel(
    const int* __restrict__ neighbor_idx,   // [N, 10]
    const float* __restrict__ features,     // [U, 256]
    float* __restrict__ out,                // [N, 256]
    int n_nodes, int blocks_per_tile)
{
    int tile = blockIdx.x / blocks_per_tile;          // 0..3
    int bid_in_tile = blockIdx.x - tile * blocks_per_tile;

    long long t = (long long)bid_in_tile * blockDim.x + threadIdx.x;
    int node  = (int)(t >> 4);                        // t / 16
    int chunk = (int)(t & 15);                        // t % 16
    if (node >= n_nodes) return;

    // chunk index within the full 256-col row
    long long c = (long long)tile * TILE_CHUNKS + chunk;

    // idx row = 40 bytes, 8B-aligned -> 5x int2 (broadcast across the node's
    // 16 threads; L1/L2-served after first touch).
    const int2* idx2 = (const int2*)(neighbor_idx + (long long)node * NUM_SAMPLE);
    int2 p0 = __ldg(idx2 + 0);
    int2 p1 = __ldg(idx2 + 1);
    int2 p2 = __ldg(idx2 + 2);
    int2 p3 = __ldg(idx2 + 3);
    int2 p4 = __ldg(idx2 + 4);

    const float4* f4 = (const float4*)features;

    // 10 independent gathered loads -> MLP=10 hides latency; within a tile
    // these hit the L2-resident 25.6 MB slice.
    float4 v0 = __ldg(f4 + (long long)p0.x * ROW_CHUNKS + c);
    float4 v1 = __ldg(f4 + (long long)p0.y * ROW_CHUNKS + c);
    float4 v2 = __ldg(f4 + (long long)p1.x * ROW_CHUNKS + c);
    float4 v3 = __ldg(f4 + (long long)p1.y * ROW_CHUNKS + c);
    float4 v4 = __ldg(f4 + (long long)p2.x * ROW_CHUNKS + c);
    float4 v5 = __ldg(f4 + (long long)p2.y * ROW_CHUNKS + c);
    float4 v6 = __ldg(f4 + (long long)p3.x * ROW_CHUNKS + c);
    float4 v7 = __ldg(f4 + (long long)p3.y * ROW_CHUNKS + c);
    float4 v8 = __ldg(f4 + (long long)p4.x * ROW_CHUNKS + c);
    float4 v9 = __ldg(f4 + (long long)p4.y * ROW_CHUNKS + c);

    float4 m;
    m.x = fmaxf(v0.x, v1.x); m.y = fmaxf(v0.y, v1.y);
    m.z = fmaxf(v0.z, v1.z); m.w = fmaxf(v0.w, v1.w);
    m.x = fmaxf(m.x, v2.x);  m.y = fmaxf(m.y, v2.y);
    m.z = fmaxf(m.z, v2.z);  m.w = fmaxf(m.w, v2.w);
    m.x = fmaxf(m.x, v3.x);  m.y = fmaxf(m.y, v3.y);
    m.z = fmaxf(m.z, v3.z);  m.w = fmaxf(m.w, v3.w);
    m.x = fmaxf(m.x, v4.x);  m.y = fmaxf(m.y, v4.y);
    m.z = fmaxf(m.z, v4.z);  m.w = fmaxf(m.w, v4.w);
    m.x = fmaxf(m.x, v5.x);  m.y = fmaxf(m.y, v5.y);
    m.z = fmaxf(m.z, v5.z);  m.w = fmaxf(m.w, v5.w);
    m.x = fmaxf(m.x, v6.x);  m.y = fmaxf(m.y, v6.y);
    m.z = fmaxf(m.z, v6.z);  m.w = fmaxf(m.w, v6.w);
    m.x = fmaxf(m.x, v7.x);  m.y = fmaxf(m.y, v7.y);
    m.z = fmaxf(m.z, v7.z);  m.w = fmaxf(m.w, v7.w);
    m.x = fmaxf(m.x, v8.x);  m.y = fmaxf(m.y, v8.y);
    m.z = fmaxf(m.z, v8.z);  m.w = fmaxf(m.w, v8.w);
    m.x = fmaxf(m.x, v9.x);  m.y = fmaxf(m.y, v9.y);
    m.z = fmaxf(m.z, v9.z);  m.w = fmaxf(m.w, v9.w);

    ((float4*)out)[(long long)node * ROW_CHUNKS + c] = m;
}

extern "C" void kernel_launch(void* const* d_in, const int* in_sizes, int n_in,
                              void* d_out, int out_size) {
    const int* neighbor_idx = (const int*)d_in[0];       // [N, 10] int32
    const float* features   = (const float*)d_in[1];     // [U, 256] fp32
    float* out = (float*)d_out;

    int n_nodes = in_sizes[0] / NUM_SAMPLE;              // 100000

    long long threads_per_tile = (long long)n_nodes * THREADS_PER_NODE;  // 1.6M
    int block = 256;
    int blocks_per_tile = (int)((threads_per_tile + block - 1) / block); // 6250
    int grid = blocks_per_tile * N_TILES;                                // 25000

    max_agg_kernel<<<grid, block>>>(neighbor_idx, features, out,
                                    n_nodes, blocks_per_tile);
}